// round 3
// baseline (speedup 1.0000x reference)
#include <cuda_runtime.h>
#include <math.h>

#define TT    1000
#define BB    128
#define NIN   85
#define NRNN  512
#define NOUT  33
#define STEP  (BB * NRNN)   /* 65536 */
#define PF    8             /* G prefetch ring depth in diag recurrence */

typedef unsigned long long u64;

// ---------------------------------------------------------------------------
// Packed f32x2 helpers (exact IEEE fp32 per lane; 2x FFMA rate on sm_103a)
// ---------------------------------------------------------------------------
__device__ __forceinline__ u64 pack2(float lo, float hi) {
    u64 r; asm("mov.b64 %0, {%1, %2};" : "=l"(r) : "f"(lo), "f"(hi)); return r;
}
__device__ __forceinline__ void unpack2(u64 v, float& lo, float& hi) {
    asm("mov.b64 {%0, %1}, %2;" : "=f"(lo), "=f"(hi) : "l"(v));
}
__device__ __forceinline__ u64 fma2(u64 a, u64 b, u64 c) {
    u64 d; asm("fma.rn.f32x2 %0, %1, %2, %3;" : "=l"(d) : "l"(a), "l"(b), "l"(c));
    return d;
}

// ---------------------------------------------------------------------------
// Scratch (__device__ globals: module-load allocated, no runtime alloc)
// ---------------------------------------------------------------------------
__device__ float g_G[(size_t)TT * BB * NRNN];      // pre-gate, 262 MB
__device__ int   g_cnt[NRNN];                      // sparse W_rec (fallback only)
__device__ int   g_idx[NRNN * NRNN];
__device__ float g_val[NRNN * NRNN];
__device__ int   g_diag;                           // 1 iff W_rec is diagonal
__device__ float g_wdiag[NRNN];                    // diagonal weight per column

// ---------------------------------------------------------------------------
// Kernel 0a: init flag
// ---------------------------------------------------------------------------
__global__ void init_kernel() { g_diag = 1; }

// ---------------------------------------------------------------------------
// Kernel 0b: parallel diagonal detection. Flat (k,n) over 512x512, coalesced
// in n. atomicAnd only fires for nonzero OFF-diagonal entries (none when
// W_rec is diagonal). Skipping exact zeros is bit-exact in fp32.
// ---------------------------------------------------------------------------
__global__ void detect_diag(const float* __restrict__ W) {
    int e = blockIdx.x * blockDim.x + threadIdx.x;   // 262144 threads
    int k = e >> 9;
    int n = e & (NRNN - 1);
    float w = W[(size_t)(NIN + k) * NRNN + n];
    if (k == n)          g_wdiag[n] = w;
    else if (w != 0.0f)  atomicAnd(&g_diag, 0);
}

// ---------------------------------------------------------------------------
// Kernel 0c: CSC build — fallback path only (predicated on !g_diag).
// One block per column; thread 0 does the ordered compaction.
// ---------------------------------------------------------------------------
__global__ void build_csc(const float* __restrict__ W) {
    if (g_diag) return;
    if (threadIdx.x != 0) return;
    int n = blockIdx.x;
    int c = 0;
    for (int k = 0; k < NRNN; k++) {
        float w = W[(size_t)(NIN + k) * NRNN + n];
        if (w != 0.0f) {
            g_idx[n * NRNN + c] = k;
            g_val[n * NRNN + c] = w;
            c++;
        }
    }
    g_cnt[n] = c;
}

// ---------------------------------------------------------------------------
// Kernel 1: G[m,n] = x[m,:] @ W_in[:,n] + b[n] + noise[m,n]
// M=128000, K=85, N=512. 64x64 tile, 4 rows x 4 cols/thread.
// ZERO per-k packs: a stored broadcast-packed, w stored col-pair-packed.
// Inner loop = 3x LDS.128 + 8x FFMA2. K-tiled (KT=48) for smem.
// ---------------------------------------------------------------------------
#define KT 48
__global__ void __launch_bounds__(256) phase1_kernel(
        const float* __restrict__ x,
        const float* __restrict__ W,
        const float* __restrict__ bias,
        const float* __restrict__ noise) {
    __shared__ u64 Ab[KT][64];       // broadcast-packed a: 24 KB
    __shared__ u64 Ws2[KT][32];      // col-pair-packed w: 12 KB

    int tid = threadIdx.x;           // 256 threads
    int m0  = blockIdx.x * 64;
    int n0  = blockIdx.y * 64;
    int tx  = tid & 15;              // col group (4 cols = 2 pairs)
    int ty  = tid >> 4;              // row group (4 rows)

    u64 acc[4][2] = {};

    for (int k0 = 0; k0 < NIN; k0 += KT) {
        int kmax = NIN - k0; if (kmax > KT) kmax = KT;
        __syncthreads();
        for (int idx = tid; idx < 64 * KT; idx += 256) {
            int r = idx / KT;
            int k = idx - r * KT;
            float a = (k < kmax) ? x[(size_t)(m0 + r) * NIN + k0 + k] : 0.0f;
            Ab[k][r] = pack2(a, a);
        }
        for (int idx = tid; idx < KT * 32; idx += 256) {
            int k  = idx >> 5;
            int j2 = idx & 31;
            if (k < kmax) {
                float2 w = *reinterpret_cast<const float2*>(
                    &W[(size_t)(k0 + k) * NRNN + n0 + j2 * 2]);
                Ws2[k][j2] = pack2(w.x, w.y);
            } else {
                Ws2[k][j2] = 0ull;
            }
        }
        __syncthreads();

        #pragma unroll 4
        for (int k = 0; k < kmax; k++) {
            ulonglong2 a01 = *reinterpret_cast<ulonglong2*>(&Ab[k][ty * 4]);
            ulonglong2 a23 = *reinterpret_cast<ulonglong2*>(&Ab[k][ty * 4 + 2]);
            ulonglong2 w   = *reinterpret_cast<ulonglong2*>(&Ws2[k][tx * 2]);
            acc[0][0] = fma2(a01.x, w.x, acc[0][0]);
            acc[0][1] = fma2(a01.x, w.y, acc[0][1]);
            acc[1][0] = fma2(a01.y, w.x, acc[1][0]);
            acc[1][1] = fma2(a01.y, w.y, acc[1][1]);
            acc[2][0] = fma2(a23.x, w.x, acc[2][0]);
            acc[2][1] = fma2(a23.x, w.y, acc[2][1]);
            acc[3][0] = fma2(a23.y, w.x, acc[3][0]);
            acc[3][1] = fma2(a23.y, w.y, acc[3][1]);
        }
    }

    float4 bb = *reinterpret_cast<const float4*>(&bias[n0 + tx * 4]);
    #pragma unroll
    for (int i = 0; i < 4; i++) {
        int m = m0 + ty * 4 + i;
        size_t off = (size_t)m * NRNN + n0 + tx * 4;
        float4 nz = *reinterpret_cast<const float4*>(&noise[off]);
        float a0, a1, a2, a3;
        unpack2(acc[i][0], a0, a1);
        unpack2(acc[i][1], a2, a3);
        float4 o;
        o.x = a0 + bb.x + nz.x;
        o.y = a1 + bb.y + nz.y;
        o.z = a2 + bb.z + nz.z;
        o.w = a3 + bb.w + nz.w;
        *reinterpret_cast<float4*>(&g_G[off]) = o;
    }
}

// ---------------------------------------------------------------------------
// Kernel 2a (fast path): pure-diagonal recurrence. Independent chains,
// h in a register, no barriers, depth-PF G prefetch ring.
// h_t = 0.8*h + 0.2*softplus(G_t + w*h)
// ---------------------------------------------------------------------------
__global__ void rec_diag_kernel(float* __restrict__ Hout) {
    if (!g_diag) return;
    int e = blockIdx.x * blockDim.x + threadIdx.x;   // 65536 threads
    int n = e & (NRNN - 1);
    float w = g_wdiag[n];

    const float* Gp = g_G + e;
    float*       Hp = Hout + e;

    float buf[PF];
    #pragma unroll
    for (int i = 0; i < PF; i++) buf[i] = Gp[(size_t)i * STEP];

    float h = 0.0f;
    for (int t0 = 0; t0 < TT; t0 += PF) {
        #pragma unroll
        for (int i = 0; i < PF; i++) {
            int t = t0 + i;
            float g = buf[i];
            int tf = t + PF;
            if (tf < TT) buf[i] = Gp[(size_t)tf * STEP];
            float acc = fmaf(w, h, g);
            float sp  = fmaxf(acc, 0.0f) + __logf(1.0f + __expf(-fabsf(acc)));
            h = 0.8f * h + 0.2f * sp;
            Hp[(size_t)t * STEP] = h;
        }
    }
}

// ---------------------------------------------------------------------------
// Kernel 2b (generic fallback): barriered sparse recurrence, one CTA/batch.
// ---------------------------------------------------------------------------
__global__ void rec_generic_kernel(float* __restrict__ Hout) {
    if (g_diag) return;
    __shared__ float hs[2][NRNN];
    int n = threadIdx.x;
    int b = blockIdx.x;

    hs[0][n] = 0.0f;

    int cnt = g_cnt[n];
    int   ki[4];
    float wv[4];
    #pragma unroll
    for (int j = 0; j < 4; j++) {
        if (j < cnt) { ki[j] = g_idx[n * NRNN + j]; wv[j] = g_val[n * NRNN + j]; }
        else         { ki[j] = 0;                    wv[j] = 0.0f; }
    }

    const float* Gb = g_G + (size_t)b * NRNN + n;
    float*       Hb = Hout + (size_t)b * NRNN + n;
    __syncthreads();

    int p = 0;
    float gcur = Gb[0];
    for (int t = 0; t < TT; t++) {
        int tn = (t + 1 < TT) ? (t + 1) : t;
        float gnext = Gb[(size_t)tn * STEP];

        float acc = gcur;
        acc = fmaf(wv[0], hs[p][ki[0]], acc);
        acc = fmaf(wv[1], hs[p][ki[1]], acc);
        acc = fmaf(wv[2], hs[p][ki[2]], acc);
        acc = fmaf(wv[3], hs[p][ki[3]], acc);
        for (int j = 4; j < cnt; j++)
            acc = fmaf(g_val[n * NRNN + j], hs[p][g_idx[n * NRNN + j]], acc);

        float sp = fmaxf(acc, 0.0f) + __logf(1.0f + __expf(-fabsf(acc)));
        float hn = 0.8f * hs[p][n] + 0.2f * sp;

        hs[p ^ 1][n] = hn;
        Hb[(size_t)t * STEP] = hn;
        __syncthreads();
        p ^= 1;
        gcur = gnext;
    }
}

// ---------------------------------------------------------------------------
// Kernel 3: y[m,o] = sigmoid(h[m,:] @ W_out[:,o] + b_out[o])
// 256 threads, 2 rows/thread, 512 rows/CTA. h pre-packed (broadcast u64)
// at staging; inner loop = 2x LDS.64 + 34x FFMA2 per kk.
// ---------------------------------------------------------------------------
#define P3BK 8
#define NO2  17   /* ceil(33/2) packed output pairs */
__global__ void __launch_bounds__(256) phase3_kernel(
        const float* __restrict__ Hin,
        const float* __restrict__ Wout,
        const float* __restrict__ bout,
        float* __restrict__ y) {
    __shared__ u64 hsh2[512][P3BK + 1];           // 36.9 KB, padded stride
    __shared__ u64 wsh2[P3BK][NO2];

    int tid = threadIdx.x;                        // 256 threads
    int m0  = blockIdx.x * 512;                   // 250 blocks

    u64 acc0[NO2] = {};
    u64 acc1[NO2] = {};

    for (int k0 = 0; k0 < NRNN; k0 += P3BK) {
        __syncthreads();
        // stage h broadcast-packed: read float2, emit two u64s
        for (int idx = tid; idx < 512 * (P3BK / 2); idx += 256) {
            int r  = idx / (P3BK / 2);
            int kp = idx - r * (P3BK / 2);
            float2 h2 = *reinterpret_cast<const float2*>(
                &Hin[(size_t)(m0 + r) * NRNN + k0 + kp * 2]);
            hsh2[r][kp * 2]     = pack2(h2.x, h2.x);
            hsh2[r][kp * 2 + 1] = pack2(h2.y, h2.y);
        }
        for (int idx = tid; idx < P3BK * NO2; idx += 256) {
            int k  = idx / NO2;
            int o2 = idx - k * NO2;
            float lo = Wout[(size_t)(k0 + k) * NOUT + 2 * o2];
            float hi = (2 * o2 + 1 < NOUT) ? Wout[(size_t)(k0 + k) * NOUT + 2 * o2 + 1] : 0.0f;
            wsh2[k][o2] = pack2(lo, hi);
        }
        __syncthreads();

        #pragma unroll
        for (int kk = 0; kk < P3BK; kk++) {
            u64 hp0 = hsh2[tid][kk];
            u64 hp1 = hsh2[tid + 256][kk];
            #pragma unroll
            for (int o2 = 0; o2 < NO2; o2++) {
                u64 w = wsh2[kk][o2];
                acc0[o2] = fma2(hp0, w, acc0[o2]);
                acc1[o2] = fma2(hp1, w, acc1[o2]);
            }
        }
    }

    int r0 = m0 + tid;
    int r1 = m0 + 256 + tid;
    #pragma unroll
    for (int o2 = 0; o2 < NO2; o2++) {
        float b0 = bout[2 * o2];
        float b1 = (2 * o2 + 1 < NOUT) ? bout[2 * o2 + 1] : 0.0f;
        float v00, v01, v10, v11;
        unpack2(acc0[o2], v00, v01);
        unpack2(acc1[o2], v10, v11);
        y[(size_t)r0 * NOUT + 2 * o2] = 1.0f / (1.0f + __expf(-(v00 + b0)));
        y[(size_t)r1 * NOUT + 2 * o2] = 1.0f / (1.0f + __expf(-(v10 + b0)));
        if (2 * o2 + 1 < NOUT) {
            y[(size_t)r0 * NOUT + 2 * o2 + 1] = 1.0f / (1.0f + __expf(-(v01 + b1)));
            y[(size_t)r1 * NOUT + 2 * o2 + 1] = 1.0f / (1.0f + __expf(-(v11 + b1)));
        }
    }
}

// ---------------------------------------------------------------------------
// Launch. Inputs: x, W, b, W_out, b_out, noise.
// Output: [y_hat (T*B*33) | h (T*B*512)] fp32.
// ---------------------------------------------------------------------------
extern "C" void kernel_launch(void* const* d_in, const int* in_sizes, int n_in,
                              void* d_out, int out_size) {
    const float* x     = (const float*)d_in[0];
    const float* W     = (const float*)d_in[1];
    const float* b     = (const float*)d_in[2];
    const float* W_out = (const float*)d_in[3];
    const float* b_out = (const float*)d_in[4];
    const float* noise = (const float*)d_in[5];

    float* y = (float*)d_out;
    float* h = (float*)d_out + (size_t)TT * BB * NOUT;

    init_kernel<<<1, 1>>>();
    detect_diag<<<(NRNN * NRNN) / 256, 256>>>(W);
    build_csc<<<NRNN, 32>>>(W);                          // fallback only
    phase1_kernel<<<dim3((TT * BB) / 64, NRNN / 64), 256>>>(x, W, b, noise);
    rec_diag_kernel<<<(BB * NRNN) / 256, 256>>>(h);      // fast path
    rec_generic_kernel<<<BB, NRNN>>>(h);                 // fallback
    phase3_kernel<<<(TT * BB) / 512, 256>>>(h, W_out, b_out, y);
}

// round 4
// speedup vs baseline: 1.1347x; 1.1347x over previous
#include <cuda_runtime.h>
#include <math.h>

#define TT    1000
#define BB    128
#define NIN   85
#define NRNN  512
#define NOUT  33
#define STEP  (BB * NRNN)   /* 65536 */
#define PF    8             /* G prefetch ring depth in diag recurrence */

typedef unsigned long long u64;

// ---------------------------------------------------------------------------
// Packed f32x2 helpers (exact IEEE fp32 per lane; 2x FFMA rate on sm_103a)
// ---------------------------------------------------------------------------
__device__ __forceinline__ u64 pack2(float lo, float hi) {
    u64 r; asm("mov.b64 %0, {%1, %2};" : "=l"(r) : "f"(lo), "f"(hi)); return r;
}
__device__ __forceinline__ void unpack2(u64 v, float& lo, float& hi) {
    asm("mov.b64 {%0, %1}, %2;" : "=f"(lo), "=f"(hi) : "l"(v));
}
__device__ __forceinline__ u64 fma2(u64 a, u64 b, u64 c) {
    u64 d; asm("fma.rn.f32x2 %0, %1, %2, %3;" : "=l"(d) : "l"(a), "l"(b), "l"(c));
    return d;
}

// ---------------------------------------------------------------------------
// Scratch (__device__ globals: module-load allocated, no runtime alloc)
// ---------------------------------------------------------------------------
__device__ float g_G[(size_t)TT * BB * NRNN];      // pre-gate, 262 MB
__device__ int   g_cnt[NRNN];                      // sparse W_rec (fallback only)
__device__ int   g_idx[NRNN * NRNN];
__device__ float g_val[NRNN * NRNN];
__device__ int   g_diag;                           // 1 iff W_rec is diagonal
__device__ float g_wdiag[NRNN];                    // diagonal weight per column

__global__ void init_kernel() { g_diag = 1; }

// Parallel diagonal detection (coalesced in n); atomicAnd fires only on
// nonzero off-diagonals. Skipping exact zeros is bit-exact in fp32.
__global__ void detect_diag(const float* __restrict__ W) {
    int e = blockIdx.x * blockDim.x + threadIdx.x;   // 262144 threads
    int k = e >> 9;
    int n = e & (NRNN - 1);
    float w = W[(size_t)(NIN + k) * NRNN + n];
    if (k == n)          g_wdiag[n] = w;
    else if (w != 0.0f)  atomicAnd(&g_diag, 0);
}

// CSC build — only runs on non-diagonal inputs (predicated on !g_diag).
__global__ void build_csc(const float* __restrict__ W) {
    if (g_diag) return;
    if (threadIdx.x != 0) return;
    int n = blockIdx.x;
    int c = 0;
    for (int k = 0; k < NRNN; k++) {
        float w = W[(size_t)(NIN + k) * NRNN + n];
        if (w != 0.0f) {
            g_idx[n * NRNN + c] = k;
            g_val[n * NRNN + c] = w;
            c++;
        }
    }
    g_cnt[n] = c;
}

// ---------------------------------------------------------------------------
// Kernel 1: G[m,n] = x[m,:] @ W_in[:,n] + b[n] + noise[m,n]
// M=128000, K=85, N=512. CTA tile 128x64, 128 threads, 8x8 per thread.
// Smem traffic = 1.0 byte/MAC (a plain float, w packed pairs) = FMA/LDS
// balanced. a packed to f32x2 in registers (alu pipe, off critical path).
// ---------------------------------------------------------------------------
#define TM 128
#define TN 64
#define KT 48
__global__ void __launch_bounds__(128) phase1_kernel(
        const float* __restrict__ x,
        const float* __restrict__ W,
        const float* __restrict__ bias,
        const float* __restrict__ noise) {
    __shared__ float As[KT][TM];         // 24.6 KB
    __shared__ u64   Ws2[KT][TN / 2];    // 12.3 KB

    int tid = threadIdx.x;               // 128 threads
    int m0  = blockIdx.x * TM;           // 1000 M-tiles
    int n0  = blockIdx.y * TN;           // 8 N-tiles
    int tx  = tid & 7;                   // col group: cols tx*8..tx*8+7 (4 pairs)
    int ty  = tid >> 3;                  // row group: rows ty*8..ty*8+7

    u64 acc[8][4] = {};

    for (int k0 = 0; k0 < NIN; k0 += KT) {
        int kmax = NIN - k0; if (kmax > KT) kmax = KT;
        __syncthreads();
        // stage x tile (row-major source, k-minor indexing => coalesced chunks)
        for (int idx = tid; idx < TM * KT; idx += 128) {
            int r = idx / KT;
            int k = idx - r * KT;
            As[k][r] = (k < kmax) ? x[(size_t)(m0 + r) * NIN + k0 + k] : 0.0f;
        }
        // stage W tile as packed column pairs
        for (int idx = tid; idx < KT * (TN / 2); idx += 128) {
            int k  = idx >> 5;
            int j2 = idx & 31;
            if (k < kmax) {
                float2 w = *reinterpret_cast<const float2*>(
                    &W[(size_t)(k0 + k) * NRNN + n0 + j2 * 2]);
                Ws2[k][j2] = pack2(w.x, w.y);
            } else {
                Ws2[k][j2] = 0ull;
            }
        }
        __syncthreads();

        #pragma unroll 2
        for (int k = 0; k < kmax; k++) {
            float4 a0 = *reinterpret_cast<float4*>(&As[k][ty * 8]);
            float4 a1 = *reinterpret_cast<float4*>(&As[k][ty * 8 + 4]);
            ulonglong2 w01 = *reinterpret_cast<ulonglong2*>(&Ws2[k][tx * 4]);
            ulonglong2 w23 = *reinterpret_cast<ulonglong2*>(&Ws2[k][tx * 4 + 2]);
            u64 ap[8] = { pack2(a0.x, a0.x), pack2(a0.y, a0.y),
                          pack2(a0.z, a0.z), pack2(a0.w, a0.w),
                          pack2(a1.x, a1.x), pack2(a1.y, a1.y),
                          pack2(a1.z, a1.z), pack2(a1.w, a1.w) };
            #pragma unroll
            for (int i = 0; i < 8; i++) {
                acc[i][0] = fma2(ap[i], w01.x, acc[i][0]);
                acc[i][1] = fma2(ap[i], w01.y, acc[i][1]);
                acc[i][2] = fma2(ap[i], w23.x, acc[i][2]);
                acc[i][3] = fma2(ap[i], w23.y, acc[i][3]);
            }
        }
    }

    float4 bb0 = *reinterpret_cast<const float4*>(&bias[n0 + tx * 8]);
    float4 bb1 = *reinterpret_cast<const float4*>(&bias[n0 + tx * 8 + 4]);
    #pragma unroll
    for (int i = 0; i < 8; i++) {
        int m = m0 + ty * 8 + i;
        size_t off = (size_t)m * NRNN + n0 + tx * 8;
        float4 nz0 = *reinterpret_cast<const float4*>(&noise[off]);
        float4 nz1 = *reinterpret_cast<const float4*>(&noise[off + 4]);
        float v0, v1, v2, v3, v4, v5, v6, v7;
        unpack2(acc[i][0], v0, v1);
        unpack2(acc[i][1], v2, v3);
        unpack2(acc[i][2], v4, v5);
        unpack2(acc[i][3], v6, v7);
        float4 o0, o1;
        o0.x = v0 + bb0.x + nz0.x;  o0.y = v1 + bb0.y + nz0.y;
        o0.z = v2 + bb0.z + nz0.z;  o0.w = v3 + bb0.w + nz0.w;
        o1.x = v4 + bb1.x + nz1.x;  o1.y = v5 + bb1.y + nz1.y;
        o1.z = v6 + bb1.z + nz1.z;  o1.w = v7 + bb1.w + nz1.w;
        *reinterpret_cast<float4*>(&g_G[off])     = o0;
        *reinterpret_cast<float4*>(&g_G[off + 4]) = o1;
    }
}

// ---------------------------------------------------------------------------
// Kernel 2a (fast path): pure-diagonal recurrence. Independent chains,
// h in a register, no barriers, depth-PF G prefetch ring.
// h_t = 0.8*h + 0.2*softplus(G_t + w*h)
// ---------------------------------------------------------------------------
__global__ void rec_diag_kernel(float* __restrict__ Hout) {
    if (!g_diag) return;
    int e = blockIdx.x * blockDim.x + threadIdx.x;   // 65536 threads
    int n = e & (NRNN - 1);
    float w = g_wdiag[n];

    const float* Gp = g_G + e;
    float*       Hp = Hout + e;

    float buf[PF];
    #pragma unroll
    for (int i = 0; i < PF; i++) buf[i] = Gp[(size_t)i * STEP];

    float h = 0.0f;
    for (int t0 = 0; t0 < TT; t0 += PF) {
        #pragma unroll
        for (int i = 0; i < PF; i++) {
            int t = t0 + i;
            float g = buf[i];
            int tf = t + PF;
            if (tf < TT) buf[i] = Gp[(size_t)tf * STEP];
            float acc = fmaf(w, h, g);
            float sp  = fmaxf(acc, 0.0f) + __logf(1.0f + __expf(-fabsf(acc)));
            h = 0.8f * h + 0.2f * sp;
            Hp[(size_t)t * STEP] = h;
        }
    }
}

// ---------------------------------------------------------------------------
// Kernel 2b (generic fallback): barriered sparse recurrence, one CTA/batch.
// ---------------------------------------------------------------------------
__global__ void rec_generic_kernel(float* __restrict__ Hout) {
    if (g_diag) return;
    __shared__ float hs[2][NRNN];
    int n = threadIdx.x;
    int b = blockIdx.x;

    hs[0][n] = 0.0f;

    int cnt = g_cnt[n];
    int   ki[4];
    float wv[4];
    #pragma unroll
    for (int j = 0; j < 4; j++) {
        if (j < cnt) { ki[j] = g_idx[n * NRNN + j]; wv[j] = g_val[n * NRNN + j]; }
        else         { ki[j] = 0;                    wv[j] = 0.0f; }
    }

    const float* Gb = g_G + (size_t)b * NRNN + n;
    float*       Hb = Hout + (size_t)b * NRNN + n;
    __syncthreads();

    int p = 0;
    float gcur = Gb[0];
    for (int t = 0; t < TT; t++) {
        int tn = (t + 1 < TT) ? (t + 1) : t;
        float gnext = Gb[(size_t)tn * STEP];

        float acc = gcur;
        acc = fmaf(wv[0], hs[p][ki[0]], acc);
        acc = fmaf(wv[1], hs[p][ki[1]], acc);
        acc = fmaf(wv[2], hs[p][ki[2]], acc);
        acc = fmaf(wv[3], hs[p][ki[3]], acc);
        for (int j = 4; j < cnt; j++)
            acc = fmaf(g_val[n * NRNN + j], hs[p][g_idx[n * NRNN + j]], acc);

        float sp = fmaxf(acc, 0.0f) + __logf(1.0f + __expf(-fabsf(acc)));
        float hn = 0.8f * hs[p][n] + 0.2f * sp;

        hs[p ^ 1][n] = hn;
        Hb[(size_t)t * STEP] = hn;
        __syncthreads();
        p ^= 1;
        gcur = gnext;
    }
}

// ---------------------------------------------------------------------------
// Kernel 3: y[m,o] = sigmoid(h[m,:] @ W_out[:,o] + b_out[o])
// 256 threads, 2 rows/thread, 512 rows/CTA, h pre-packed at staging.
// ---------------------------------------------------------------------------
#define P3BK 8
#define NO2  17   /* ceil(33/2) packed output pairs */
__global__ void __launch_bounds__(256) phase3_kernel(
        const float* __restrict__ Hin,
        const float* __restrict__ Wout,
        const float* __restrict__ bout,
        float* __restrict__ y) {
    __shared__ u64 hsh2[512][P3BK + 1];           // 36.9 KB, padded stride
    __shared__ u64 wsh2[P3BK][NO2];

    int tid = threadIdx.x;                        // 256 threads
    int m0  = blockIdx.x * 512;                   // 250 blocks

    u64 acc0[NO2] = {};
    u64 acc1[NO2] = {};

    for (int k0 = 0; k0 < NRNN; k0 += P3BK) {
        __syncthreads();
        for (int idx = tid; idx < 512 * (P3BK / 2); idx += 256) {
            int r  = idx / (P3BK / 2);
            int kp = idx - r * (P3BK / 2);
            float2 h2 = *reinterpret_cast<const float2*>(
                &Hin[(size_t)(m0 + r) * NRNN + k0 + kp * 2]);
            hsh2[r][kp * 2]     = pack2(h2.x, h2.x);
            hsh2[r][kp * 2 + 1] = pack2(h2.y, h2.y);
        }
        for (int idx = tid; idx < P3BK * NO2; idx += 256) {
            int k  = idx / NO2;
            int o2 = idx - k * NO2;
            float lo = Wout[(size_t)(k0 + k) * NOUT + 2 * o2];
            float hi = (2 * o2 + 1 < NOUT) ? Wout[(size_t)(k0 + k) * NOUT + 2 * o2 + 1] : 0.0f;
            wsh2[k][o2] = pack2(lo, hi);
        }
        __syncthreads();

        #pragma unroll
        for (int kk = 0; kk < P3BK; kk++) {
            u64 hp0 = hsh2[tid][kk];
            u64 hp1 = hsh2[tid + 256][kk];
            #pragma unroll
            for (int o2 = 0; o2 < NO2; o2++) {
                u64 w = wsh2[kk][o2];
                acc0[o2] = fma2(hp0, w, acc0[o2]);
                acc1[o2] = fma2(hp1, w, acc1[o2]);
            }
        }
    }

    int r0 = m0 + tid;
    int r1 = m0 + 256 + tid;
    #pragma unroll
    for (int o2 = 0; o2 < NO2; o2++) {
        float b0 = bout[2 * o2];
        float b1 = (2 * o2 + 1 < NOUT) ? bout[2 * o2 + 1] : 0.0f;
        float v00, v01, v10, v11;
        unpack2(acc0[o2], v00, v01);
        unpack2(acc1[o2], v10, v11);
        y[(size_t)r0 * NOUT + 2 * o2] = 1.0f / (1.0f + __expf(-(v00 + b0)));
        y[(size_t)r1 * NOUT + 2 * o2] = 1.0f / (1.0f + __expf(-(v10 + b0)));
        if (2 * o2 + 1 < NOUT) {
            y[(size_t)r0 * NOUT + 2 * o2 + 1] = 1.0f / (1.0f + __expf(-(v01 + b1)));
            y[(size_t)r1 * NOUT + 2 * o2 + 1] = 1.0f / (1.0f + __expf(-(v11 + b1)));
        }
    }
}

// ---------------------------------------------------------------------------
// Launch. Inputs: x, W, b, W_out, b_out, noise.
// Output: [y_hat (T*B*33) | h (T*B*512)] fp32.
// ---------------------------------------------------------------------------
extern "C" void kernel_launch(void* const* d_in, const int* in_sizes, int n_in,
                              void* d_out, int out_size) {
    const float* x     = (const float*)d_in[0];
    const float* W     = (const float*)d_in[1];
    const float* b     = (const float*)d_in[2];
    const float* W_out = (const float*)d_in[3];
    const float* b_out = (const float*)d_in[4];
    const float* noise = (const float*)d_in[5];

    float* y = (float*)d_out;
    float* h = (float*)d_out + (size_t)TT * BB * NOUT;

    init_kernel<<<1, 1>>>();
    detect_diag<<<(NRNN * NRNN) / 256, 256>>>(W);
    build_csc<<<NRNN, 32>>>(W);                              // fallback only
    phase1_kernel<<<dim3((TT * BB) / TM, NRNN / TN), 128>>>(x, W, b, noise);
    rec_diag_kernel<<<(BB * NRNN) / 256, 256>>>(h);          // fast path
    rec_generic_kernel<<<BB, NRNN>>>(h);                     // fallback
    phase3_kernel<<<(TT * BB) / 512, 256>>>(h, W_out, b_out, y);
}

// round 6
// speedup vs baseline: 1.3394x; 1.1804x over previous
#include <cuda_runtime.h>
#include <math.h>

#define TT    1000
#define BB    128
#define NIN   85
#define NRNN  512
#define NOUT  33
#define STEP  (BB * NRNN)   /* 65536 */
#define PF    8             /* G prefetch ring depth in diag recurrence */

typedef unsigned long long u64;

// ---------------------------------------------------------------------------
// Packed f32x2 helpers (exact IEEE fp32 per lane; 2x FFMA rate on sm_103a)
// ---------------------------------------------------------------------------
__device__ __forceinline__ u64 pack2(float lo, float hi) {
    u64 r; asm("mov.b64 %0, {%1, %2};" : "=l"(r) : "f"(lo), "f"(hi)); return r;
}
__device__ __forceinline__ void unpack2(u64 v, float& lo, float& hi) {
    asm("mov.b64 {%0, %1}, %2;" : "=f"(lo), "=f"(hi) : "l"(v));
}
__device__ __forceinline__ u64 fma2(u64 a, u64 b, u64 c) {
    u64 d; asm("fma.rn.f32x2 %0, %1, %2, %3;" : "=l"(d) : "l"(a), "l"(b), "l"(c));
    return d;
}

// ---------------------------------------------------------------------------
// Scratch (__device__ globals: module-load allocated, no runtime alloc)
// ---------------------------------------------------------------------------
__device__ float g_G[(size_t)TT * BB * NRNN];      // pre-gate, 262 MB
__device__ int   g_cnt[NRNN];                      // sparse W_rec (fallback only)
__device__ int   g_idx[NRNN * NRNN];
__device__ float g_val[NRNN * NRNN];
__device__ int   g_diag;                           // 1 iff W_rec is diagonal
__device__ float g_wdiag[NRNN];                    // diagonal weight per column

__global__ void init_kernel() { g_diag = 1; }

// Parallel diagonal detection (coalesced in n); atomicAnd fires only on
// nonzero off-diagonals. Skipping exact zeros is bit-exact in fp32.
__global__ void detect_diag(const float* __restrict__ W) {
    int e = blockIdx.x * blockDim.x + threadIdx.x;   // 262144 threads
    int k = e >> 9;
    int n = e & (NRNN - 1);
    float w = W[(size_t)(NIN + k) * NRNN + n];
    if (k == n)          g_wdiag[n] = w;
    else if (w != 0.0f)  atomicAnd(&g_diag, 0);
}

// CSC build — only runs on non-diagonal inputs (predicated on !g_diag).
__global__ void build_csc(const float* __restrict__ W) {
    if (g_diag) return;
    if (threadIdx.x != 0) return;
    int n = blockIdx.x;
    int c = 0;
    for (int k = 0; k < NRNN; k++) {
        float w = W[(size_t)(NIN + k) * NRNN + n];
        if (w != 0.0f) {
            g_idx[n * NRNN + c] = k;
            g_val[n * NRNN + c] = w;
            c++;
        }
    }
    g_cnt[n] = c;
}

// ---------------------------------------------------------------------------
// Kernel 1: G[m,n] = x[m,:] @ W_in[:,n] + b[n] + noise[m,n]
// M=128000, K=85, N=512. CTA tile 128x64, 128 threads, 8x8 per thread.
// As rows padded to TM+4=132 floats (528 B = 33*16): float4 reads stay
// 16B-aligned, staging STS bank = (4k+r)%32 -> 4-way (was 32-way at
// stride 512B). Inner loop = 1.0 smem byte/MAC, FFMA2-bound.
// ---------------------------------------------------------------------------
#define TM 128
#define TMP (TM + 4)                     /* padded row: 528 B, 16B-aligned */
#define TN 64
#define KT 48
__global__ void __launch_bounds__(128) phase1_kernel(
        const float* __restrict__ x,
        const float* __restrict__ W,
        const float* __restrict__ bias,
        const float* __restrict__ noise) {
    __shared__ float As[KT][TMP];        // 25.3 KB
    __shared__ u64   Ws2[KT][TN / 2];    // 12.3 KB

    int tid = threadIdx.x;               // 128 threads
    int m0  = blockIdx.x * TM;           // 1000 M-tiles
    int n0  = blockIdx.y * TN;           // 8 N-tiles
    int tx  = tid & 7;                   // col group: cols tx*8..tx*8+7 (4 pairs)
    int ty  = tid >> 3;                  // row group: rows ty*8..ty*8+7

    u64 acc[8][4] = {};

    for (int k0 = 0; k0 < NIN; k0 += KT) {
        int kmax = NIN - k0; if (kmax > KT) kmax = KT;
        __syncthreads();
        // stage x tile: warp reads 32 consecutive k of one row (coalesced);
        // padded stride makes the transposed STS 4-way instead of 32-way
        for (int idx = tid; idx < TM * KT; idx += 128) {
            int r = idx / KT;
            int k = idx - r * KT;
            As[k][r] = (k < kmax) ? x[(size_t)(m0 + r) * NIN + k0 + k] : 0.0f;
        }
        // stage W tile as packed column pairs (consecutive u64 -> no conflict)
        for (int idx = tid; idx < KT * (TN / 2); idx += 128) {
            int k  = idx >> 5;
            int j2 = idx & 31;
            if (k < kmax) {
                float2 w = *reinterpret_cast<const float2*>(
                    &W[(size_t)(k0 + k) * NRNN + n0 + j2 * 2]);
                Ws2[k][j2] = pack2(w.x, w.y);
            } else {
                Ws2[k][j2] = 0ull;
            }
        }
        __syncthreads();

        #pragma unroll 2
        for (int k = 0; k < kmax; k++) {
            float4 a0 = *reinterpret_cast<float4*>(&As[k][ty * 8]);
            float4 a1 = *reinterpret_cast<float4*>(&As[k][ty * 8 + 4]);
            ulonglong2 w01 = *reinterpret_cast<ulonglong2*>(&Ws2[k][tx * 4]);
            ulonglong2 w23 = *reinterpret_cast<ulonglong2*>(&Ws2[k][tx * 4 + 2]);
            u64 ap[8] = { pack2(a0.x, a0.x), pack2(a0.y, a0.y),
                          pack2(a0.z, a0.z), pack2(a0.w, a0.w),
                          pack2(a1.x, a1.x), pack2(a1.y, a1.y),
                          pack2(a1.z, a1.z), pack2(a1.w, a1.w) };
            #pragma unroll
            for (int i = 0; i < 8; i++) {
                acc[i][0] = fma2(ap[i], w01.x, acc[i][0]);
                acc[i][1] = fma2(ap[i], w01.y, acc[i][1]);
                acc[i][2] = fma2(ap[i], w23.x, acc[i][2]);
                acc[i][3] = fma2(ap[i], w23.y, acc[i][3]);
            }
        }
    }

    float4 bb0 = *reinterpret_cast<const float4*>(&bias[n0 + tx * 8]);
    float4 bb1 = *reinterpret_cast<const float4*>(&bias[n0 + tx * 8 + 4]);
    #pragma unroll
    for (int i = 0; i < 8; i++) {
        int m = m0 + ty * 8 + i;
        size_t off = (size_t)m * NRNN + n0 + tx * 8;
        float4 nz0 = *reinterpret_cast<const float4*>(&noise[off]);
        float4 nz1 = *reinterpret_cast<const float4*>(&noise[off + 4]);
        float v0, v1, v2, v3, v4, v5, v6, v7;
        unpack2(acc[i][0], v0, v1);
        unpack2(acc[i][1], v2, v3);
        unpack2(acc[i][2], v4, v5);
        unpack2(acc[i][3], v6, v7);
        float4 o0, o1;
        o0.x = v0 + bb0.x + nz0.x;  o0.y = v1 + bb0.y + nz0.y;
        o0.z = v2 + bb0.z + nz0.z;  o0.w = v3 + bb0.w + nz0.w;
        o1.x = v4 + bb1.x + nz1.x;  o1.y = v5 + bb1.y + nz1.y;
        o1.z = v6 + bb1.z + nz1.z;  o1.w = v7 + bb1.w + nz1.w;
        *reinterpret_cast<float4*>(&g_G[off])     = o0;
        *reinterpret_cast<float4*>(&g_G[off + 4]) = o1;
    }
}

// ---------------------------------------------------------------------------
// Kernel 2a (fast path): pure-diagonal recurrence. Independent chains,
// h in a register, no barriers, depth-PF G prefetch ring.
// h_t = 0.8*h + 0.2*softplus(G_t + w*h)
// ---------------------------------------------------------------------------
__global__ void rec_diag_kernel(float* __restrict__ Hout) {
    if (!g_diag) return;
    int e = blockIdx.x * blockDim.x + threadIdx.x;   // 65536 threads
    int n = e & (NRNN - 1);
    float w = g_wdiag[n];

    const float* Gp = g_G + e;
    float*       Hp = Hout + e;

    float buf[PF];
    #pragma unroll
    for (int i = 0; i < PF; i++) buf[i] = Gp[(size_t)i * STEP];

    float h = 0.0f;
    for (int t0 = 0; t0 < TT; t0 += PF) {
        #pragma unroll
        for (int i = 0; i < PF; i++) {
            int t = t0 + i;
            float g = buf[i];
            int tf = t + PF;
            if (tf < TT) buf[i] = Gp[(size_t)tf * STEP];
            float acc = fmaf(w, h, g);
            float sp  = fmaxf(acc, 0.0f) + __logf(1.0f + __expf(-fabsf(acc)));
            h = 0.8f * h + 0.2f * sp;
            Hp[(size_t)t * STEP] = h;
        }
    }
}

// ---------------------------------------------------------------------------
// Kernel 2b (generic fallback): barriered sparse recurrence, one CTA/batch.
// ---------------------------------------------------------------------------
__global__ void rec_generic_kernel(float* __restrict__ Hout) {
    if (g_diag) return;
    __shared__ float hs[2][NRNN];
    int n = threadIdx.x;
    int b = blockIdx.x;

    hs[0][n] = 0.0f;

    int cnt = g_cnt[n];
    int   ki[4];
    float wv[4];
    #pragma unroll
    for (int j = 0; j < 4; j++) {
        if (j < cnt) { ki[j] = g_idx[n * NRNN + j]; wv[j] = g_val[n * NRNN + j]; }
        else         { ki[j] = 0;                    wv[j] = 0.0f; }
    }

    const float* Gb = g_G + (size_t)b * NRNN + n;
    float*       Hb = Hout + (size_t)b * NRNN + n;
    __syncthreads();

    int p = 0;
    float gcur = Gb[0];
    for (int t = 0; t < TT; t++) {
        int tn = (t + 1 < TT) ? (t + 1) : t;
        float gnext = Gb[(size_t)tn * STEP];

        float acc = gcur;
        acc = fmaf(wv[0], hs[p][ki[0]], acc);
        acc = fmaf(wv[1], hs[p][ki[1]], acc);
        acc = fmaf(wv[2], hs[p][ki[2]], acc);
        acc = fmaf(wv[3], hs[p][ki[3]], acc);
        for (int j = 4; j < cnt; j++)
            acc = fmaf(g_val[n * NRNN + j], hs[p][g_idx[n * NRNN + j]], acc);

        float sp = fmaxf(acc, 0.0f) + __logf(1.0f + __expf(-fabsf(acc)));
        float hn = 0.8f * hs[p][n] + 0.2f * sp;

        hs[p ^ 1][n] = hn;
        Hb[(size_t)t * STEP] = hn;
        __syncthreads();
        p ^= 1;
        gcur = gnext;
    }
}

// ---------------------------------------------------------------------------
// Kernel 3: y[m,o] = sigmoid(h[m,:] @ W_out[:,o] + b_out[o])
// 256 threads, 2 rows/thread, 512 rows/CTA, h pre-packed at staging.
// ---------------------------------------------------------------------------
#define P3BK 8
#define NO2  17   /* ceil(33/2) packed output pairs */
__global__ void __launch_bounds__(256) phase3_kernel(
        const float* __restrict__ Hin,
        const float* __restrict__ Wout,
        const float* __restrict__ bout,
        float* __restrict__ y) {
    __shared__ u64 hsh2[512][P3BK + 1];           // 36.9 KB, padded stride
    __shared__ u64 wsh2[P3BK][NO2];

    int tid = threadIdx.x;                        // 256 threads
    int m0  = blockIdx.x * 512;                   // 250 blocks

    u64 acc0[NO2] = {};
    u64 acc1[NO2] = {};

    for (int k0 = 0; k0 < NRNN; k0 += P3BK) {
        __syncthreads();
        for (int idx = tid; idx < 512 * (P3BK / 2); idx += 256) {
            int r  = idx / (P3BK / 2);
            int kp = idx - r * (P3BK / 2);
            float2 h2 = *reinterpret_cast<const float2*>(
                &Hin[(size_t)(m0 + r) * NRNN + k0 + kp * 2]);
            hsh2[r][kp * 2]     = pack2(h2.x, h2.x);
            hsh2[r][kp * 2 + 1] = pack2(h2.y, h2.y);
        }
        for (int idx = tid; idx < P3BK * NO2; idx += 256) {
            int k  = idx / NO2;
            int o2 = idx - k * NO2;
            float lo = Wout[(size_t)(k0 + k) * NOUT + 2 * o2];
            float hi = (2 * o2 + 1 < NOUT) ? Wout[(size_t)(k0 + k) * NOUT + 2 * o2 + 1] : 0.0f;
            wsh2[k][o2] = pack2(lo, hi);
        }
        __syncthreads();

        #pragma unroll
        for (int kk = 0; kk < P3BK; kk++) {
            u64 hp0 = hsh2[tid][kk];
            u64 hp1 = hsh2[tid + 256][kk];
            #pragma unroll
            for (int o2 = 0; o2 < NO2; o2++) {
                u64 w = wsh2[kk][o2];
                acc0[o2] = fma2(hp0, w, acc0[o2]);
                acc1[o2] = fma2(hp1, w, acc1[o2]);
            }
        }
    }

    int r0 = m0 + tid;
    int r1 = m0 + 256 + tid;
    #pragma unroll
    for (int o2 = 0; o2 < NO2; o2++) {
        float b0 = bout[2 * o2];
        float b1 = (2 * o2 + 1 < NOUT) ? bout[2 * o2 + 1] : 0.0f;
        float v00, v01, v10, v11;
        unpack2(acc0[o2], v00, v01);
        unpack2(acc1[o2], v10, v11);
        y[(size_t)r0 * NOUT + 2 * o2] = 1.0f / (1.0f + __expf(-(v00 + b0)));
        y[(size_t)r1 * NOUT + 2 * o2] = 1.0f / (1.0f + __expf(-(v10 + b0)));
        if (2 * o2 + 1 < NOUT) {
            y[(size_t)r0 * NOUT + 2 * o2 + 1] = 1.0f / (1.0f + __expf(-(v01 + b1)));
            y[(size_t)r1 * NOUT + 2 * o2 + 1] = 1.0f / (1.0f + __expf(-(v11 + b1)));
        }
    }
}

// ---------------------------------------------------------------------------
// Launch. Inputs: x, W, b, W_out, b_out, noise.
// Output: [y_hat (T*B*33) | h (T*B*512)] fp32.
// ---------------------------------------------------------------------------
extern "C" void kernel_launch(void* const* d_in, const int* in_sizes, int n_in,
                              void* d_out, int out_size) {
    const float* x     = (const float*)d_in[0];
    const float* W     = (const float*)d_in[1];
    const float* b     = (const float*)d_in[2];
    const float* W_out = (const float*)d_in[3];
    const float* b_out = (const float*)d_in[4];
    const float* noise = (const float*)d_in[5];

    float* y = (float*)d_out;
    float* h = (float*)d_out + (size_t)TT * BB * NOUT;

    init_kernel<<<1, 1>>>();
    detect_diag<<<(NRNN * NRNN) / 256, 256>>>(W);
    build_csc<<<NRNN, 32>>>(W);                              // fallback only
    phase1_kernel<<<dim3((TT * BB) / TM, NRNN / TN), 128>>>(x, W, b, noise);
    rec_diag_kernel<<<(BB * NRNN) / 256, 256>>>(h);          // fast path
    rec_generic_kernel<<<BB, NRNN>>>(h);                     // fallback
    phase3_kernel<<<(TT * BB) / 512, 256>>>(h, W_out, b_out, y);
}

// round 7
// speedup vs baseline: 1.3710x; 1.0236x over previous
#include <cuda_runtime.h>
#include <math.h>

#define TT    1000
#define BB    128
#define NIN   85
#define NRNN  512
#define NOUT  33
#define STEP  (BB * NRNN)   /* 65536 */
#define PF    8             /* G prefetch ring depth in diag recurrence */

typedef unsigned long long u64;

// ---------------------------------------------------------------------------
// Packed f32x2 helpers (exact IEEE fp32 per lane; 2x FFMA rate on sm_103a)
// ---------------------------------------------------------------------------
__device__ __forceinline__ u64 pack2(float lo, float hi) {
    u64 r; asm("mov.b64 %0, {%1, %2};" : "=l"(r) : "f"(lo), "f"(hi)); return r;
}
__device__ __forceinline__ void unpack2(u64 v, float& lo, float& hi) {
    asm("mov.b64 {%0, %1}, %2;" : "=f"(lo), "=f"(hi) : "l"(v));
}
__device__ __forceinline__ u64 fma2(u64 a, u64 b, u64 c) {
    u64 d; asm("fma.rn.f32x2 %0, %1, %2, %3;" : "=l"(d) : "l"(a), "l"(b), "l"(c));
    return d;
}

// ---------------------------------------------------------------------------
// Scratch (__device__ globals: module-load allocated, no runtime alloc)
// ---------------------------------------------------------------------------
__device__ float g_G[(size_t)TT * BB * NRNN];      // pre-gate, 262 MB
__device__ int   g_cnt[NRNN];                      // sparse W_rec (fallback only)
__device__ int   g_idx[NRNN * NRNN];
__device__ float g_val[NRNN * NRNN];
__device__ int   g_diag;                           // 1 iff W_rec is diagonal
__device__ float g_wdiag[NRNN];                    // diagonal weight per column

__global__ void init_kernel() { g_diag = 1; }

// Parallel diagonal detection (coalesced in n); atomicAnd fires only on
// nonzero off-diagonals. Skipping exact zeros is bit-exact in fp32.
__global__ void detect_diag(const float* __restrict__ W) {
    int e = blockIdx.x * blockDim.x + threadIdx.x;   // 262144 threads
    int k = e >> 9;
    int n = e & (NRNN - 1);
    float w = W[(size_t)(NIN + k) * NRNN + n];
    if (k == n)          g_wdiag[n] = w;
    else if (w != 0.0f)  atomicAnd(&g_diag, 0);
}

// CSC build — only runs on non-diagonal inputs (predicated on !g_diag).
__global__ void build_csc(const float* __restrict__ W) {
    if (g_diag) return;
    if (threadIdx.x != 0) return;
    int n = blockIdx.x;
    int c = 0;
    for (int k = 0; k < NRNN; k++) {
        float w = W[(size_t)(NIN + k) * NRNN + n];
        if (w != 0.0f) {
            g_idx[n * NRNN + c] = k;
            g_val[n * NRNN + c] = w;
            c++;
        }
    }
    g_cnt[n] = c;
}

// ---------------------------------------------------------------------------
// Kernel 1: G[m,n] = x[m,:] @ W_in[:,n] + b[n] + noise[m,n]
// M=128000, K=85, N=512. CTA tile 128x64, 128 threads, 8x8 per thread.
// As rows padded to 132 floats (16B-aligned, 4-way staging STS).
// launch_bounds(128,5): reg cap 102 -> 5 CTAs/SM (was reg-capped at 4).
// ---------------------------------------------------------------------------
#define TM 128
#define TMP (TM + 4)                     /* padded row: 528 B, 16B-aligned */
#define TN 64
#define KT 48
__global__ void __launch_bounds__(128, 5) phase1_kernel(
        const float* __restrict__ x,
        const float* __restrict__ W,
        const float* __restrict__ bias,
        const float* __restrict__ noise) {
    __shared__ float As[KT][TMP];        // 25.3 KB
    __shared__ u64   Ws2[KT][TN / 2];    // 12.3 KB

    int tid = threadIdx.x;               // 128 threads
    int m0  = blockIdx.x * TM;           // 1000 M-tiles
    int n0  = blockIdx.y * TN;           // 8 N-tiles
    int tx  = tid & 7;                   // col group: cols tx*8..tx*8+7 (4 pairs)
    int ty  = tid >> 3;                  // row group: rows ty*8..ty*8+7

    u64 acc[8][4] = {};

    for (int k0 = 0; k0 < NIN; k0 += KT) {
        int kmax = NIN - k0; if (kmax > KT) kmax = KT;
        __syncthreads();
        for (int idx = tid; idx < TM * KT; idx += 128) {
            int r = idx / KT;
            int k = idx - r * KT;
            As[k][r] = (k < kmax) ? x[(size_t)(m0 + r) * NIN + k0 + k] : 0.0f;
        }
        for (int idx = tid; idx < KT * (TN / 2); idx += 128) {
            int k  = idx >> 5;
            int j2 = idx & 31;
            if (k < kmax) {
                float2 w = *reinterpret_cast<const float2*>(
                    &W[(size_t)(k0 + k) * NRNN + n0 + j2 * 2]);
                Ws2[k][j2] = pack2(w.x, w.y);
            } else {
                Ws2[k][j2] = 0ull;
            }
        }
        __syncthreads();

        #pragma unroll 2
        for (int k = 0; k < kmax; k++) {
            float4 a0 = *reinterpret_cast<float4*>(&As[k][ty * 8]);
            float4 a1 = *reinterpret_cast<float4*>(&As[k][ty * 8 + 4]);
            ulonglong2 w01 = *reinterpret_cast<ulonglong2*>(&Ws2[k][tx * 4]);
            ulonglong2 w23 = *reinterpret_cast<ulonglong2*>(&Ws2[k][tx * 4 + 2]);
            u64 ap[8] = { pack2(a0.x, a0.x), pack2(a0.y, a0.y),
                          pack2(a0.z, a0.z), pack2(a0.w, a0.w),
                          pack2(a1.x, a1.x), pack2(a1.y, a1.y),
                          pack2(a1.z, a1.z), pack2(a1.w, a1.w) };
            #pragma unroll
            for (int i = 0; i < 8; i++) {
                acc[i][0] = fma2(ap[i], w01.x, acc[i][0]);
                acc[i][1] = fma2(ap[i], w01.y, acc[i][1]);
                acc[i][2] = fma2(ap[i], w23.x, acc[i][2]);
                acc[i][3] = fma2(ap[i], w23.y, acc[i][3]);
            }
        }
    }

    float4 bb0 = *reinterpret_cast<const float4*>(&bias[n0 + tx * 8]);
    float4 bb1 = *reinterpret_cast<const float4*>(&bias[n0 + tx * 8 + 4]);
    #pragma unroll
    for (int i = 0; i < 8; i++) {
        int m = m0 + ty * 8 + i;
        size_t off = (size_t)m * NRNN + n0 + tx * 8;
        float4 nz0 = *reinterpret_cast<const float4*>(&noise[off]);
        float4 nz1 = *reinterpret_cast<const float4*>(&noise[off + 4]);
        float v0, v1, v2, v3, v4, v5, v6, v7;
        unpack2(acc[i][0], v0, v1);
        unpack2(acc[i][1], v2, v3);
        unpack2(acc[i][2], v4, v5);
        unpack2(acc[i][3], v6, v7);
        float4 o0, o1;
        o0.x = v0 + bb0.x + nz0.x;  o0.y = v1 + bb0.y + nz0.y;
        o0.z = v2 + bb0.z + nz0.z;  o0.w = v3 + bb0.w + nz0.w;
        o1.x = v4 + bb1.x + nz1.x;  o1.y = v5 + bb1.y + nz1.y;
        o1.z = v6 + bb1.z + nz1.z;  o1.w = v7 + bb1.w + nz1.w;
        *reinterpret_cast<float4*>(&g_G[off])     = o0;
        *reinterpret_cast<float4*>(&g_G[off + 4]) = o1;
    }
}

// ---------------------------------------------------------------------------
// Kernel 2a (fast path): pure-diagonal recurrence. Independent chains,
// h in a register, no barriers, depth-PF G prefetch ring.
// ---------------------------------------------------------------------------
__global__ void rec_diag_kernel(float* __restrict__ Hout) {
    if (!g_diag) return;
    int e = blockIdx.x * blockDim.x + threadIdx.x;   // 65536 threads
    int n = e & (NRNN - 1);
    float w = g_wdiag[n];

    const float* Gp = g_G + e;
    float*       Hp = Hout + e;

    float buf[PF];
    #pragma unroll
    for (int i = 0; i < PF; i++) buf[i] = Gp[(size_t)i * STEP];

    float h = 0.0f;
    for (int t0 = 0; t0 < TT; t0 += PF) {
        #pragma unroll
        for (int i = 0; i < PF; i++) {
            int t = t0 + i;
            float g = buf[i];
            int tf = t + PF;
            if (tf < TT) buf[i] = Gp[(size_t)tf * STEP];
            float acc = fmaf(w, h, g);
            float sp  = fmaxf(acc, 0.0f) + __logf(1.0f + __expf(-fabsf(acc)));
            h = 0.8f * h + 0.2f * sp;
            Hp[(size_t)t * STEP] = h;
        }
    }
}

// ---------------------------------------------------------------------------
// Kernel 2b (generic fallback): barriered sparse recurrence, one CTA/batch.
// ---------------------------------------------------------------------------
__global__ void rec_generic_kernel(float* __restrict__ Hout) {
    if (g_diag) return;
    __shared__ float hs[2][NRNN];
    int n = threadIdx.x;
    int b = blockIdx.x;

    hs[0][n] = 0.0f;

    int cnt = g_cnt[n];
    int   ki[4];
    float wv[4];
    #pragma unroll
    for (int j = 0; j < 4; j++) {
        if (j < cnt) { ki[j] = g_idx[n * NRNN + j]; wv[j] = g_val[n * NRNN + j]; }
        else         { ki[j] = 0;                    wv[j] = 0.0f; }
    }

    const float* Gb = g_G + (size_t)b * NRNN + n;
    float*       Hb = Hout + (size_t)b * NRNN + n;
    __syncthreads();

    int p = 0;
    float gcur = Gb[0];
    for (int t = 0; t < TT; t++) {
        int tn = (t + 1 < TT) ? (t + 1) : t;
        float gnext = Gb[(size_t)tn * STEP];

        float acc = gcur;
        acc = fmaf(wv[0], hs[p][ki[0]], acc);
        acc = fmaf(wv[1], hs[p][ki[1]], acc);
        acc = fmaf(wv[2], hs[p][ki[2]], acc);
        acc = fmaf(wv[3], hs[p][ki[3]], acc);
        for (int j = 4; j < cnt; j++)
            acc = fmaf(g_val[n * NRNN + j], hs[p][g_idx[n * NRNN + j]], acc);

        float sp = fmaxf(acc, 0.0f) + __logf(1.0f + __expf(-fabsf(acc)));
        float hn = 0.8f * hs[p][n] + 0.2f * sp;

        hs[p ^ 1][n] = hn;
        Hb[(size_t)t * STEP] = hn;
        __syncthreads();
        p ^= 1;
        gcur = gnext;
    }
}

// ---------------------------------------------------------------------------
// Kernel 3: y[m,o] = sigmoid(h[m,:] @ W_out[:,o] + b_out[o])
// o2-split: warps 0-3 own output pairs 0..8, warps 4-7 own 9..16.
// Each thread: 4 interleaved rows (r = t + i*128, conflict-free stride-9 LDS).
// Per kk: 4 h-loads + <=9 w-loads + 36 FFMA2 -> FFMA2-bound.
// ---------------------------------------------------------------------------
#define P3BK 8
#define P3PAD (P3BK + 1)   /* 9 floats: odd stride, conflict-free */
#define NO2  17            /* ceil(33/2) packed output pairs */
#define NO2G 9             /* o2 pairs per thread group */
__global__ void __launch_bounds__(256) phase3_kernel(
        const float* __restrict__ Hin,
        const float* __restrict__ Wout,
        const float* __restrict__ bout,
        float* __restrict__ y) {
    __shared__ float hsh[512][P3PAD];             // 18.4 KB
    __shared__ u64   wsh2[P3BK][NO2];             // 1.1 KB

    int tid = threadIdx.x;                        // 256 threads
    int g   = tid >> 7;                           // warp-uniform group
    int t   = tid & 127;
    int m0  = blockIdx.x * 512;                   // 250 blocks
    int ob  = g * NO2G;                           // o2 base: 0 or 9

    u64 acc[4][NO2G] = {};

    for (int k0 = 0; k0 < NRNN; k0 += P3BK) {
        __syncthreads();
        for (int idx = tid; idx < 512 * P3BK; idx += 256) {
            int r = idx >> 3;
            int k = idx & (P3BK - 1);
            hsh[r][k] = Hin[(size_t)(m0 + r) * NRNN + k0 + k];
        }
        for (int idx = tid; idx < P3BK * NO2; idx += 256) {
            int k  = idx / NO2;
            int o2 = idx - k * NO2;
            float lo = Wout[(size_t)(k0 + k) * NOUT + 2 * o2];
            float hi = (2 * o2 + 1 < NOUT) ? Wout[(size_t)(k0 + k) * NOUT + 2 * o2 + 1] : 0.0f;
            wsh2[k][o2] = pack2(lo, hi);
        }
        __syncthreads();

        #pragma unroll
        for (int kk = 0; kk < P3BK; kk++) {
            u64 hp[4];
            #pragma unroll
            for (int i = 0; i < 4; i++) {
                float hv = hsh[t + i * 128][kk];
                hp[i] = pack2(hv, hv);
            }
            #pragma unroll
            for (int j = 0; j < NO2G; j++) {
                int o2 = ob + j;
                u64 w = (o2 < NO2) ? wsh2[kk][o2] : 0ull;
                #pragma unroll
                for (int i = 0; i < 4; i++)
                    acc[i][j] = fma2(hp[i], w, acc[i][j]);
            }
        }
    }

    #pragma unroll
    for (int j = 0; j < NO2G; j++) {
        int o2 = ob + j;
        if (o2 >= NO2) continue;
        float b0 = bout[2 * o2];
        float b1 = (2 * o2 + 1 < NOUT) ? bout[2 * o2 + 1] : 0.0f;
        #pragma unroll
        for (int i = 0; i < 4; i++) {
            int r = m0 + t + i * 128;
            float v0, v1;
            unpack2(acc[i][j], v0, v1);
            y[(size_t)r * NOUT + 2 * o2] = 1.0f / (1.0f + __expf(-(v0 + b0)));
            if (2 * o2 + 1 < NOUT)
                y[(size_t)r * NOUT + 2 * o2 + 1] = 1.0f / (1.0f + __expf(-(v1 + b1)));
        }
    }
}

// ---------------------------------------------------------------------------
// Launch. Inputs: x, W, b, W_out, b_out, noise.
// Output: [y_hat (T*B*33) | h (T*B*512)] fp32.
// ---------------------------------------------------------------------------
extern "C" void kernel_launch(void* const* d_in, const int* in_sizes, int n_in,
                              void* d_out, int out_size) {
    const float* x     = (const float*)d_in[0];
    const float* W     = (const float*)d_in[1];
    const float* b     = (const float*)d_in[2];
    const float* W_out = (const float*)d_in[3];
    const float* b_out = (const float*)d_in[4];
    const float* noise = (const float*)d_in[5];

    float* y = (float*)d_out;
    float* h = (float*)d_out + (size_t)TT * BB * NOUT;

    init_kernel<<<1, 1>>>();
    detect_diag<<<(NRNN * NRNN) / 256, 256>>>(W);
    build_csc<<<NRNN, 32>>>(W);                              // fallback only
    phase1_kernel<<<dim3((TT * BB) / TM, NRNN / TN), 128>>>(x, W, b, noise);
    rec_diag_kernel<<<(BB * NRNN) / 256, 256>>>(h);          // fast path
    rec_generic_kernel<<<BB, NRNN>>>(h);                     // fallback
    phase3_kernel<<<(TT * BB) / 512, 256>>>(h, W_out, b_out, y);
}

// round 8
// speedup vs baseline: 1.4818x; 1.0808x over previous
#include <cuda_runtime.h>
#include <math.h>

#define TT    1000
#define BB    128
#define NIN   85
#define NRNN  512
#define NOUT  33
#define MM    (TT * BB)     /* 128000 rows */
#define STEP  (BB * NRNN)   /* 65536 */
#define PF    8             /* G prefetch ring depth in diag recurrence */

typedef unsigned long long u64;

// ---------------------------------------------------------------------------
// Packed f32x2 helpers (exact IEEE fp32 per lane; 2x FFMA rate on sm_103a)
// ---------------------------------------------------------------------------
__device__ __forceinline__ u64 pack2(float lo, float hi) {
    u64 r; asm("mov.b64 %0, {%1, %2};" : "=l"(r) : "f"(lo), "f"(hi)); return r;
}
__device__ __forceinline__ void unpack2(u64 v, float& lo, float& hi) {
    asm("mov.b64 {%0, %1}, %2;" : "=f"(lo), "=f"(hi) : "l"(v));
}
__device__ __forceinline__ u64 fma2(u64 a, u64 b, u64 c) {
    u64 d; asm("fma.rn.f32x2 %0, %1, %2, %3;" : "=l"(d) : "l"(a), "l"(b), "l"(c));
    return d;
}

// ---------------------------------------------------------------------------
// Scratch (__device__ globals: module-load allocated, no runtime alloc)
// ---------------------------------------------------------------------------
__device__ float g_G[(size_t)TT * BB * NRNN];      // pre-gate, 262 MB
__device__ float g_xT[(size_t)NIN * MM];           // transposed x, 43.5 MB
__device__ int   g_cnt[NRNN];                      // sparse W_rec (fallback only)
__device__ int   g_idx[NRNN * NRNN];
__device__ float g_val[NRNN * NRNN];
__device__ int   g_diag;                           // 1 iff W_rec is diagonal
__device__ float g_wdiag[NRNN];                    // diagonal weight per column

__global__ void init_kernel() { g_diag = 1; }

// Parallel diagonal detection (coalesced in n); atomicAnd fires only on
// nonzero off-diagonals. Skipping exact zeros is bit-exact in fp32.
__global__ void detect_diag(const float* __restrict__ W) {
    int e = blockIdx.x * blockDim.x + threadIdx.x;   // 262144 threads
    int k = e >> 9;
    int n = e & (NRNN - 1);
    float w = W[(size_t)(NIN + k) * NRNN + n];
    if (k == n)          g_wdiag[n] = w;
    else if (w != 0.0f)  atomicAnd(&g_diag, 0);
}

// CSC build — only runs on non-diagonal inputs (predicated on !g_diag).
__global__ void build_csc(const float* __restrict__ W) {
    if (g_diag) return;
    if (threadIdx.x != 0) return;
    int n = blockIdx.x;
    int c = 0;
    for (int k = 0; k < NRNN; k++) {
        float w = W[(size_t)(NIN + k) * NRNN + n];
        if (w != 0.0f) {
            g_idx[n * NRNN + c] = k;
            g_val[n * NRNN + c] = w;
            c++;
        }
    }
    g_cnt[n] = c;
}

// ---------------------------------------------------------------------------
// Kernel 0d: global transpose x[M,85] -> xT[85,M]. Shared 32x32 tile.
// Coalesced LDG (consecutive k in a row) and STG (consecutive m in a row).
// One-shot ~87 MB traffic; removes ALL transpose cost from phase1 staging.
// ---------------------------------------------------------------------------
__global__ void transpose_x(const float* __restrict__ x) {
    __shared__ float tile[32][33];
    int mb = blockIdx.x * 32;            // 4000 blocks
    int kb = blockIdx.y * 32;            // 3 blocks (85 -> 96 padded by guard)
    int tx = threadIdx.x;                // 32
    int ty = threadIdx.y;                // 8
    #pragma unroll
    for (int i = ty; i < 32; i += 8) {
        int k = kb + tx;
        tile[i][tx] = (k < NIN) ? x[(size_t)(mb + i) * NIN + k] : 0.0f;
    }
    __syncthreads();
    #pragma unroll
    for (int i = ty; i < 32; i += 8) {
        int k = kb + i;
        if (k < NIN) g_xT[(size_t)k * MM + mb + tx] = tile[tx][i];
    }
}

// ---------------------------------------------------------------------------
// Kernel 1: G[m,n] = x[m,:] @ W_in[:,n] + b[n] + noise[m,n]
// M=128000, K=85, N=512. CTA tile 128x64, 128 threads, 8x8 per thread.
// Stages from g_xT: LDG.128 coalesced + STS.128 conflict-free (no transpose
// in staging). As rows padded to 132 floats for 16B-aligned float4 reads.
// ---------------------------------------------------------------------------
#define TM 128
#define TMP (TM + 4)                     /* padded row: 528 B, 16B-aligned */
#define TN 64
#define KT 48
__global__ void __launch_bounds__(128, 5) phase1_kernel(
        const float* __restrict__ W,
        const float* __restrict__ bias,
        const float* __restrict__ noise) {
    __shared__ float As[KT][TMP];        // 25.3 KB
    __shared__ u64   Ws2[KT][TN / 2];    // 12.3 KB

    int tid = threadIdx.x;               // 128 threads
    int m0  = blockIdx.x * TM;           // 1000 M-tiles
    int n0  = blockIdx.y * TN;           // 8 N-tiles
    int tx  = tid & 7;                   // col group: cols tx*8..tx*8+7 (4 pairs)
    int ty  = tid >> 3;                  // row group: rows ty*8..ty*8+7

    u64 acc[8][4] = {};

    for (int k0 = 0; k0 < NIN; k0 += KT) {
        int kmax = NIN - k0; if (kmax > KT) kmax = KT;
        __syncthreads();
        // stage xT tile: fixed k, 32 consecutive float4 of m.
        // LDG.128 coalesced; STS.128 to consecutive addresses: conflict-free.
        for (int idx = tid; idx < KT * (TM / 4); idx += 128) {
            int k  = idx >> 5;           // TM/4 = 32
            int r4 = idx & 31;
            float4 v;
            if (k < kmax)
                v = *reinterpret_cast<const float4*>(
                        &g_xT[(size_t)(k0 + k) * MM + m0 + r4 * 4]);
            else
                v = make_float4(0.f, 0.f, 0.f, 0.f);
            *reinterpret_cast<float4*>(&As[k][r4 * 4]) = v;
        }
        // stage W tile as packed column pairs (consecutive u64 -> no conflict)
        for (int idx = tid; idx < KT * (TN / 2); idx += 128) {
            int k  = idx >> 5;
            int j2 = idx & 31;
            if (k < kmax) {
                float2 w = *reinterpret_cast<const float2*>(
                    &W[(size_t)(k0 + k) * NRNN + n0 + j2 * 2]);
                Ws2[k][j2] = pack2(w.x, w.y);
            } else {
                Ws2[k][j2] = 0ull;
            }
        }
        __syncthreads();

        #pragma unroll 2
        for (int k = 0; k < kmax; k++) {
            float4 a0 = *reinterpret_cast<float4*>(&As[k][ty * 8]);
            float4 a1 = *reinterpret_cast<float4*>(&As[k][ty * 8 + 4]);
            ulonglong2 w01 = *reinterpret_cast<ulonglong2*>(&Ws2[k][tx * 4]);
            ulonglong2 w23 = *reinterpret_cast<ulonglong2*>(&Ws2[k][tx * 4 + 2]);
            u64 ap[8] = { pack2(a0.x, a0.x), pack2(a0.y, a0.y),
                          pack2(a0.z, a0.z), pack2(a0.w, a0.w),
                          pack2(a1.x, a1.x), pack2(a1.y, a1.y),
                          pack2(a1.z, a1.z), pack2(a1.w, a1.w) };
            #pragma unroll
            for (int i = 0; i < 8; i++) {
                acc[i][0] = fma2(ap[i], w01.x, acc[i][0]);
                acc[i][1] = fma2(ap[i], w01.y, acc[i][1]);
                acc[i][2] = fma2(ap[i], w23.x, acc[i][2]);
                acc[i][3] = fma2(ap[i], w23.y, acc[i][3]);
            }
        }
    }

    float4 bb0 = *reinterpret_cast<const float4*>(&bias[n0 + tx * 8]);
    float4 bb1 = *reinterpret_cast<const float4*>(&bias[n0 + tx * 8 + 4]);
    #pragma unroll
    for (int i = 0; i < 8; i++) {
        int m = m0 + ty * 8 + i;
        size_t off = (size_t)m * NRNN + n0 + tx * 8;
        float4 nz0 = *reinterpret_cast<const float4*>(&noise[off]);
        float4 nz1 = *reinterpret_cast<const float4*>(&noise[off + 4]);
        float v0, v1, v2, v3, v4, v5, v6, v7;
        unpack2(acc[i][0], v0, v1);
        unpack2(acc[i][1], v2, v3);
        unpack2(acc[i][2], v4, v5);
        unpack2(acc[i][3], v6, v7);
        float4 o0, o1;
        o0.x = v0 + bb0.x + nz0.x;  o0.y = v1 + bb0.y + nz0.y;
        o0.z = v2 + bb0.z + nz0.z;  o0.w = v3 + bb0.w + nz0.w;
        o1.x = v4 + bb1.x + nz1.x;  o1.y = v5 + bb1.y + nz1.y;
        o1.z = v6 + bb1.z + nz1.z;  o1.w = v7 + bb1.w + nz1.w;
        *reinterpret_cast<float4*>(&g_G[off])     = o0;
        *reinterpret_cast<float4*>(&g_G[off + 4]) = o1;
    }
}

// ---------------------------------------------------------------------------
// Kernel 2a (fast path): pure-diagonal recurrence. Independent chains,
// h in a register, no barriers, depth-PF G prefetch ring.
// ---------------------------------------------------------------------------
__global__ void rec_diag_kernel(float* __restrict__ Hout) {
    if (!g_diag) return;
    int e = blockIdx.x * blockDim.x + threadIdx.x;   // 65536 threads
    int n = e & (NRNN - 1);
    float w = g_wdiag[n];

    const float* Gp = g_G + e;
    float*       Hp = Hout + e;

    float buf[PF];
    #pragma unroll
    for (int i = 0; i < PF; i++) buf[i] = Gp[(size_t)i * STEP];

    float h = 0.0f;
    for (int t0 = 0; t0 < TT; t0 += PF) {
        #pragma unroll
        for (int i = 0; i < PF; i++) {
            int t = t0 + i;
            float g = buf[i];
            int tf = t + PF;
            if (tf < TT) buf[i] = Gp[(size_t)tf * STEP];
            float acc = fmaf(w, h, g);
            float sp  = fmaxf(acc, 0.0f) + __logf(1.0f + __expf(-fabsf(acc)));
            h = 0.8f * h + 0.2f * sp;
            Hp[(size_t)t * STEP] = h;
        }
    }
}

// ---------------------------------------------------------------------------
// Kernel 2b (generic fallback): barriered sparse recurrence, one CTA/batch.
// ---------------------------------------------------------------------------
__global__ void rec_generic_kernel(float* __restrict__ Hout) {
    if (g_diag) return;
    __shared__ float hs[2][NRNN];
    int n = threadIdx.x;
    int b = blockIdx.x;

    hs[0][n] = 0.0f;

    int cnt = g_cnt[n];
    int   ki[4];
    float wv[4];
    #pragma unroll
    for (int j = 0; j < 4; j++) {
        if (j < cnt) { ki[j] = g_idx[n * NRNN + j]; wv[j] = g_val[n * NRNN + j]; }
        else         { ki[j] = 0;                    wv[j] = 0.0f; }
    }

    const float* Gb = g_G + (size_t)b * NRNN + n;
    float*       Hb = Hout + (size_t)b * NRNN + n;
    __syncthreads();

    int p = 0;
    float gcur = Gb[0];
    for (int t = 0; t < TT; t++) {
        int tn = (t + 1 < TT) ? (t + 1) : t;
        float gnext = Gb[(size_t)tn * STEP];

        float acc = gcur;
        acc = fmaf(wv[0], hs[p][ki[0]], acc);
        acc = fmaf(wv[1], hs[p][ki[1]], acc);
        acc = fmaf(wv[2], hs[p][ki[2]], acc);
        acc = fmaf(wv[3], hs[p][ki[3]], acc);
        for (int j = 4; j < cnt; j++)
            acc = fmaf(g_val[n * NRNN + j], hs[p][g_idx[n * NRNN + j]], acc);

        float sp = fmaxf(acc, 0.0f) + __logf(1.0f + __expf(-fabsf(acc)));
        float hn = 0.8f * hs[p][n] + 0.2f * sp;

        hs[p ^ 1][n] = hn;
        Hb[(size_t)t * STEP] = hn;
        __syncthreads();
        p ^= 1;
        gcur = gnext;
    }
}

// ---------------------------------------------------------------------------
// Kernel 3: y[m,o] = sigmoid(h[m,:] @ W_out[:,o] + b_out[o])
// o2-split: warps 0-3 own output pairs 0..8, warps 4-7 own 9..16.
// Each thread: 4 interleaved rows (r = t + i*128, conflict-free stride-9 LDS).
// ---------------------------------------------------------------------------
#define P3BK 8
#define P3PAD (P3BK + 1)   /* 9 floats: odd stride, conflict-free */
#define NO2  17            /* ceil(33/2) packed output pairs */
#define NO2G 9             /* o2 pairs per thread group */
__global__ void __launch_bounds__(256) phase3_kernel(
        const float* __restrict__ Hin,
        const float* __restrict__ Wout,
        const float* __restrict__ bout,
        float* __restrict__ y) {
    __shared__ float hsh[512][P3PAD];             // 18.4 KB
    __shared__ u64   wsh2[P3BK][NO2];             // 1.1 KB

    int tid = threadIdx.x;                        // 256 threads
    int g   = tid >> 7;                           // warp-uniform group
    int t   = tid & 127;
    int m0  = blockIdx.x * 512;                   // 250 blocks
    int ob  = g * NO2G;                           // o2 base: 0 or 9

    u64 acc[4][NO2G] = {};

    for (int k0 = 0; k0 < NRNN; k0 += P3BK) {
        __syncthreads();
        for (int idx = tid; idx < 512 * P3BK; idx += 256) {
            int r = idx >> 3;
            int k = idx & (P3BK - 1);
            hsh[r][k] = Hin[(size_t)(m0 + r) * NRNN + k0 + k];
        }
        for (int idx = tid; idx < P3BK * NO2; idx += 256) {
            int k  = idx / NO2;
            int o2 = idx - k * NO2;
            float lo = Wout[(size_t)(k0 + k) * NOUT + 2 * o2];
            float hi = (2 * o2 + 1 < NOUT) ? Wout[(size_t)(k0 + k) * NOUT + 2 * o2 + 1] : 0.0f;
            wsh2[k][o2] = pack2(lo, hi);
        }
        __syncthreads();

        #pragma unroll
        for (int kk = 0; kk < P3BK; kk++) {
            u64 hp[4];
            #pragma unroll
            for (int i = 0; i < 4; i++) {
                float hv = hsh[t + i * 128][kk];
                hp[i] = pack2(hv, hv);
            }
            #pragma unroll
            for (int j = 0; j < NO2G; j++) {
                int o2 = ob + j;
                u64 w = (o2 < NO2) ? wsh2[kk][o2] : 0ull;
                #pragma unroll
                for (int i = 0; i < 4; i++)
                    acc[i][j] = fma2(hp[i], w, acc[i][j]);
            }
        }
    }

    #pragma unroll
    for (int j = 0; j < NO2G; j++) {
        int o2 = ob + j;
        if (o2 >= NO2) continue;
        float b0 = bout[2 * o2];
        float b1 = (2 * o2 + 1 < NOUT) ? bout[2 * o2 + 1] : 0.0f;
        #pragma unroll
        for (int i = 0; i < 4; i++) {
            int r = m0 + t + i * 128;
            float v0, v1;
            unpack2(acc[i][j], v0, v1);
            y[(size_t)r * NOUT + 2 * o2] = 1.0f / (1.0f + __expf(-(v0 + b0)));
            if (2 * o2 + 1 < NOUT)
                y[(size_t)r * NOUT + 2 * o2 + 1] = 1.0f / (1.0f + __expf(-(v1 + b1)));
        }
    }
}

// ---------------------------------------------------------------------------
// Launch. Inputs: x, W, b, W_out, b_out, noise.
// Output: [y_hat (T*B*33) | h (T*B*512)] fp32.
// ---------------------------------------------------------------------------
extern "C" void kernel_launch(void* const* d_in, const int* in_sizes, int n_in,
                              void* d_out, int out_size) {
    const float* x     = (const float*)d_in[0];
    const float* W     = (const float*)d_in[1];
    const float* b     = (const float*)d_in[2];
    const float* W_out = (const float*)d_in[3];
    const float* b_out = (const float*)d_in[4];
    const float* noise = (const float*)d_in[5];

    float* y = (float*)d_out;
    float* h = (float*)d_out + (size_t)TT * BB * NOUT;

    init_kernel<<<1, 1>>>();
    detect_diag<<<(NRNN * NRNN) / 256, 256>>>(W);
    build_csc<<<NRNN, 32>>>(W);                              // fallback only
    transpose_x<<<dim3(MM / 32, (NIN + 31) / 32), dim3(32, 8)>>>(x);
    phase1_kernel<<<dim3(MM / TM, NRNN / TN), 128>>>(W, b, noise);
    rec_diag_kernel<<<(BB * NRNN) / 256, 256>>>(h);          // fast path
    rec_generic_kernel<<<BB, NRNN>>>(h);                     // fallback
    phase3_kernel<<<(TT * BB) / 512, 256>>>(h, W_out, b_out, y);
}